// round 9
// baseline (speedup 1.0000x reference)
#include <cuda_runtime.h>
#include <cuda_fp16.h>
#include <math.h>
#include <stdint.h>

#define CB   512
#define CS   120
#define CD   216
#define CH   1024
#define CML  24

#define NCH_X 4
#define NT    32        // N tiles of 128 cols (4 gates x 32 j)
#define MT    64        // M tile per CTA
#define NK16  80        // 16 x k16-blocks (K 216->256 padded) + 64 h k16-blocks
#define FSTRIDE 1024    // uint4s per k16 block: 32 mblk * 32 lane

#define SGJ 33
#define SMEM_STEP (4 * MT * SGJ * 4)   // 33792 (epilogue gate exchange only)

// ---------------- device globals ----------------
// W in B-fragment layout: uint4[ ((nt*4+gate)*20 + ch)*4 + k16 ][64]  (flat f strides 64)
__device__ __align__(16) uint4 g_Wfrag[(size_t)NT * 4 * NK16 * 64];        // 10.5MB
// A in A-fragment layout: [k16 block][mblk][lane] -> uint4 (a0..a3)
__device__ __align__(16) uint4 g_xfrag[(size_t)CS * 16 * FSTRIDE];         // 31.5MB
__device__ __align__(16) uint4 g_xdfrag[16 * FSTRIDE];                     // 256KB
__device__ __align__(16) uint4 g_hfrag[2][64 * FSTRIDE];                   // 2x1MB
__device__ __align__(16) __half g_h[2][(size_t)CB * CH];                   // row-major (proj)
__device__ float g_c[(size_t)CB * CH];
__device__ float g_bias[4 * CH];

// ---------------- helpers ----------------
__device__ __forceinline__ void mma_h(float* d, const uint32_t* a, uint32_t b0, uint32_t b1) {
    asm volatile("mma.sync.aligned.m16n8k16.row.col.f32.f16.f16.f32 "
        "{%0,%1,%2,%3}, {%4,%5,%6,%7}, {%8,%9}, {%0,%1,%2,%3};"
        : "+f"(d[0]), "+f"(d[1]), "+f"(d[2]), "+f"(d[3])
        : "r"(a[0]), "r"(a[1]), "r"(a[2]), "r"(a[3]), "r"(b0), "r"(b1));
}
__device__ __forceinline__ float sigf(float x) { return 1.0f / (1.0f + __expf(-x)); }
__device__ __forceinline__ uint32_t packh2(float a, float b) {
    return (uint32_t)__half_as_ushort(__float2half_rn(a)) |
           ((uint32_t)__half_as_ushort(__float2half_rn(b)) << 16);
}

// ---------------- init / precompute ----------------
__global__ void init_kernel(const float* __restrict__ b_ih, const float* __restrict__ b_hh) {
    int idx = blockIdx.x * blockDim.x + threadIdx.x;
    if (idx < CB * CH) g_c[idx] = 0.0f;
    if (idx < 64 * FSTRIDE) g_hfrag[0][idx] = make_uint4(0, 0, 0, 0);
    if (idx < 16 * FSTRIDE) g_xdfrag[idx] = make_uint4(0, 0, 0, 0);
    if (idx < 4 * CH) g_bias[idx] = b_ih[idx] + b_hh[idx];
}

// src (B,S,D) fp32 -> per-t A-fragment planes (zero-padded K 216->256)
__global__ void prep_x_kernel(const float* __restrict__ src) {
    size_t idx = (size_t)blockIdx.x * blockDim.x + threadIdx.x;
    if (idx >= (size_t)CS * 16 * FSTRIDE) return;
    int lane = (int)(idx & 31);
    int mblk = (int)((idx >> 5) & 31);
    int k16  = (int)((idx >> 10) & 15);
    int t    = (int)(idx >> 14);
    int r0 = mblk * 16 + (lane >> 2);
    int c0 = k16 * 16 + (lane & 3) * 2;
    const float* sp = src + (size_t)r0 * CS * CD + (size_t)t * CD;
    const float* sp8 = sp + (size_t)8 * CS * CD;
    float v00 = (c0     < CD) ? sp [c0]     : 0.0f;
    float v01 = (c0 + 1 < CD) ? sp [c0 + 1] : 0.0f;
    float v80 = (c0     < CD) ? sp8[c0]     : 0.0f;
    float v81 = (c0 + 1 < CD) ? sp8[c0 + 1] : 0.0f;
    float v08 = (c0 + 8 < CD) ? sp [c0 + 8] : 0.0f;
    float v09 = (c0 + 9 < CD) ? sp [c0 + 9] : 0.0f;
    float v88 = (c0 + 8 < CD) ? sp8[c0 + 8] : 0.0f;
    float v89 = (c0 + 9 < CD) ? sp8[c0 + 9] : 0.0f;
    g_xfrag[idx] = make_uint4(packh2(v00, v01), packh2(v80, v81),
                              packh2(v08, v09), packh2(v88, v89));
}

// W -> B-fragment layout (fp16). One thread per uint2 (4 fp16: k0,k1,k8,k9).
__global__ void prep_w_kernel(const float* __restrict__ W_ih, const float* __restrict__ W_hh) {
    int s = blockIdx.x * blockDim.x + threadIdx.x;
    const int TOT = NT * 4 * NK16 * 128;
    if (s >= TOT) return;
    int nb   = s & 3;
    int lane = (s >> 2) & 31;
    int k16  = (s >> 7) & 3;
    int rest = s >> 9;
    int ch = rest % 20; rest /= 20;
    int wc = rest & 3;          // gate
    int nt = rest >> 2;

    int j = nt * 32 + nb * 8 + (lane >> 2);
    int R = wc * CH + j;
    int k0 = k16 * 16 + (lane & 3) * 2;

    float v[4];
    if (ch < NCH_X) {
        int kb = ch * 64 + k0;
        int ks[4] = {kb, kb + 1, kb + 8, kb + 9};
#pragma unroll
        for (int q = 0; q < 4; ++q)
            v[q] = (ks[q] < CD) ? W_ih[(size_t)R * CD + ks[q]] : 0.0f;
    } else {
        const float* wr = W_hh + (size_t)R * CH + (ch - NCH_X) * 64 + k0;
        v[0] = wr[0]; v[1] = wr[1]; v[2] = wr[8]; v[3] = wr[9];
    }
    size_t dest = ((((size_t)(nt * 4 + wc) * 20 + ch) * 4 + k16)) * 128 + lane * 4 + nb;
    ((uint2*)g_Wfrag)[dest] = make_uint2(packh2(v[0], v[1]), packh2(v[2], v[3]));
}

// ---------------- fused LSTM step: barrier-free mainloop, all-LDG operands ----------------
__global__ __launch_bounds__(256, 2)
void lstm_step(int use_xd, int t, int rd, int wr)
{
    extern __shared__ char smem[];
    const int tid = threadIdx.x;
    const int lane = tid & 31;
    const int w = tid >> 5;
    const int wm = w & 1;          // 2 row groups of 32
    const int wn = w >> 1;         // gate 0..3
    const int nt = blockIdx.x;
    const int mb = blockIdx.y * MT;

    const uint4* xf = use_xd ? g_xdfrag : (g_xfrag + (size_t)t * 16 * FSTRIDE);
    const uint4* hf = g_hfrag[rd];
    const int mblk0 = (mb >> 4) + wm * 2;
    const uint32_t aoff0 = (uint32_t)((mblk0 + 0) * 32 + lane);
    const uint32_t aoff1 = (uint32_t)((mblk0 + 1) * 32 + lane);

    auto aptr = [&](int f, uint32_t off) -> const uint4* {
        return (f < 16 ? xf + (size_t)f * FSTRIDE
                       : hf + (size_t)(f - 16) * FSTRIDE) + off;
    };

    // W fragment pointer; flat f strides 64 uint4
    const uint4* wbase = g_Wfrag + ((size_t)(nt * 4 + wn) * NK16) * 64 + lane * 2;

    float acc[2][4][4];
#pragma unroll
    for (int mg = 0; mg < 2; ++mg)
#pragma unroll
        for (int nb = 0; nb < 4; ++nb)
#pragma unroll
            for (int e = 0; e < 4; ++e) acc[mg][nb][e] = 0.0f;

    // prologue: A slots 0,1 ; W slots 0,1,2
    uint4 af0[2], af1[2];
    af0[0] = __ldg(aptr(0, aoff0)); af0[1] = __ldg(aptr(0, aoff1));
    af1[0] = __ldg(aptr(1, aoff0)); af1[1] = __ldg(aptr(1, aoff1));
    uint4 wr0[4], wr1[4];
#pragma unroll
    for (int s = 0; s < 3; ++s) {
        const uint4* np = wbase + (size_t)s * 64;
        wr0[s] = __ldg(np); wr1[s] = __ldg(np + 1);
    }

#pragma unroll 1
    for (int fo = 0; fo < NK16; fo += 4) {
#pragma unroll
        for (int fi = 0; fi < 4; ++fi) {
            const int f = fo + fi;
            // W prefetch f+3 into free slot (fi+3)&3
            if (f + 3 < NK16) {
                const uint4* np = wbase + (size_t)(f + 3) * 64;
                wr0[(fi + 3) & 3] = __ldg(np);
                wr1[(fi + 3) & 3] = __ldg(np + 1);
            }
            uint32_t b0[4] = {wr0[fi].x, wr0[fi].z, wr1[fi].x, wr1[fi].z};
            uint32_t b1[4] = {wr0[fi].y, wr0[fi].w, wr1[fi].y, wr1[fi].w};
            uint4* As = (fi & 1) ? af1 : af0;
            const uint32_t* a0 = (const uint32_t*)&As[0];
            const uint32_t* a1 = (const uint32_t*)&As[1];
#pragma unroll
            for (int nb = 0; nb < 4; ++nb) {
                mma_h(acc[0][nb], a0, b0[nb], b1[nb]);
                mma_h(acc[1][nb], a1, b0[nb], b1[nb]);
            }
            // A prefetch f+2 into the slot just consumed
            if (f + 2 < NK16) {
                As[0] = __ldg(aptr(f + 2, aoff0));
                As[1] = __ldg(aptr(f + 2, aoff1));
            }
        }
    }

    // gate exchange via smem
    float* sg = (float*)smem;
#pragma unroll
    for (int mg = 0; mg < 2; ++mg)
#pragma unroll
        for (int nb = 0; nb < 4; ++nb) {
            int r0 = wm * 32 + mg * 16 + (lane >> 2);
            int jj = nb * 8 + (lane & 3) * 2;
            float* p0 = &sg[((size_t)(wn * MT + r0)) * SGJ + jj];
            p0[0] = acc[mg][nb][0]; p0[1] = acc[mg][nb][1];
            float* p1 = p0 + 8 * SGJ;
            p1[0] = acc[mg][nb][2]; p1[1] = acc[mg][nb][3];
        }
    __syncthreads();

    // cell update: 64 rows x 32 j -> 256 threads x (1 row, 8 j)
    {
        int row = tid >> 2;            // local row 0..63
        int j0 = (tid & 3) * 8;
        int jcol = nt * 32 + j0;
        size_t off = (size_t)(mb + row) * CH + jcol;

        float gv[4][8];
#pragma unroll
        for (int g = 0; g < 4; ++g) {
            const float* p = &sg[((size_t)(g * MT + row)) * SGJ + j0];
#pragma unroll
            for (int e = 0; e < 8; ++e) gv[g][e] = p[e] + g_bias[g * CH + jcol + e];
        }
        float4 cA = *(const float4*)(g_c + off);
        float4 cB = *(const float4*)(g_c + off + 4);
        float cold[8] = {cA.x, cA.y, cA.z, cA.w, cB.x, cB.y, cB.z, cB.w};
        float cn[8], hn[8];
#pragma unroll
        for (int e = 0; e < 8; ++e) {
            float ci = sigf(gv[0][e]);
            float cf = sigf(gv[1][e]);
            float cg = tanhf(gv[2][e]);
            float co = sigf(gv[3][e]);
            cn[e] = cf * cold[e] + ci * cg;
            hn[e] = co * tanhf(cn[e]);
        }
        *(float4*)(g_c + off)     = make_float4(cn[0], cn[1], cn[2], cn[3]);
        *(float4*)(g_c + off + 4) = make_float4(cn[4], cn[5], cn[6], cn[7]);

        uint32_t ph[4];
#pragma unroll
        for (int e2 = 0; e2 < 4; ++e2)
            ph[e2] = packh2(hn[e2 * 2], hn[e2 * 2 + 1]);

        // row-major h (for proj)
        *(uint4*)(&g_h[wr][off]) = make_uint4(ph[0], ph[1], ph[2], ph[3]);

        // fragment-layout h
        int grow = mb + row;
        int mblkr = grow >> 4;
        int rloc = grow & 15;
        int rr = rloc & 7, rhi = rloc >> 3;
        int k16f = (nt * 32 + j0) >> 4;
        int reg = ((tid & 1) << 1) + rhi;     // chalf*2 + rhi ; chalf = (tid&3)&1
        uint32_t* hf4 = (uint32_t*)(g_hfrag[wr]) + ((size_t)(k16f * 32 + mblkr) * 32) * 4;
#pragma unroll
        for (int jp = 0; jp < 4; ++jp)
            hf4[(rr * 4 + jp) * 4 + reg] = ph[jp];
    }
}

// ---------------- decoder projection ----------------
__global__ __launch_bounds__(256)
void proj_kernel(int hbuf,
                 const float* __restrict__ W_out,
                 const float* __restrict__ b_out,
                 float* __restrict__ outp)
{
    int lane = threadIdx.x & 31;
    int w = threadIdx.x >> 5;
    int d = blockIdx.x * 8 + w;
    int r0 = blockIdx.y * 8;
    const __half* hp = g_h[hbuf];
    int k0 = lane * 32;

    float wv[32];
    {
        const float4* wp = (const float4*)(W_out + (size_t)d * CH + k0);
#pragma unroll
        for (int q = 0; q < 8; ++q) {
            float4 f = wp[q];
            wv[q * 4 + 0] = f.x; wv[q * 4 + 1] = f.y; wv[q * 4 + 2] = f.z; wv[q * 4 + 3] = f.w;
        }
    }
    float acc[8];
#pragma unroll
    for (int r = 0; r < 8; ++r) {
        const uint4* hq = (const uint4*)(hp + (size_t)(r0 + r) * CH + k0);
        float s = 0.0f;
#pragma unroll
        for (int q = 0; q < 4; ++q) {
            uint4 hv = hq[q];
            const __half2* h2 = (const __half2*)&hv;
#pragma unroll
            for (int e = 0; e < 4; ++e) {
                float2 a = __half22float2(h2[e]);
                int kk = q * 8 + e * 2;
                s += a.x * wv[kk] + a.y * wv[kk + 1];
            }
        }
        acc[r] = s;
    }
#pragma unroll
    for (int r = 0; r < 8; ++r) {
#pragma unroll
        for (int off = 16; off > 0; off >>= 1)
            acc[r] += __shfl_xor_sync(0xFFFFFFFFu, acc[r], off);
    }
    if (lane == 0) {
        float bo = b_out[d];
        int k16 = d >> 4;
        int cc = d & 15;
        int regbase = (cc >= 8) ? 2 : 0;
        int lane_t = ((cc & 7) >> 1) ;        // + rr*4 added per row
        int hsel = cc & 1;
#pragma unroll
        for (int r = 0; r < 8; ++r) {
            float y = acc[r] + bo;
            int row = r0 + r;
            outp[(size_t)row * CML * CD + d] = y;
            // write fragment-layout decoder x
            int mblk = row >> 4;
            int rloc = row & 15;
            int rr = rloc & 7, rhi = rloc >> 3;
            int reg = regbase + rhi;
            __half* base = (__half*)g_xdfrag;
            base[(((size_t)k16 * 32 + mblk) * 32 + (rr * 4 + lane_t)) * 8 + reg * 2 + hsel] =
                __float2half_rn(y);
        }
    }
}

extern "C" void kernel_launch(void* const* d_in, const int* in_sizes, int n_in,
                              void* d_out, int out_size)
{
    (void)in_sizes; (void)n_in; (void)out_size;
    const float* src   = (const float*)d_in[0];
    const float* W_ih  = (const float*)d_in[1];
    const float* W_hh  = (const float*)d_in[2];
    const float* b_ih  = (const float*)d_in[3];
    const float* b_hh  = (const float*)d_in[4];
    const float* W_out = (const float*)d_in[5];
    const float* b_out = (const float*)d_in[6];
    float* out = (float*)d_out;

    static int once = 0;
    if (!once) {
        cudaFuncSetAttribute(lstm_step, cudaFuncAttributeMaxDynamicSharedMemorySize, SMEM_STEP);
        once = 1;
    }

    init_kernel<<<(CB * CH + 255) / 256, 256>>>(b_ih, b_hh);
    {
        size_t tot = (size_t)CS * 16 * FSTRIDE;
        prep_x_kernel<<<(unsigned)((tot + 255) / 256), 256>>>(src);
    }
    {
        int tot = NT * 4 * NK16 * 128;
        prep_w_kernel<<<(tot + 255) / 256, 256>>>(W_ih, W_hh);
    }

    dim3 sgrid(NT, CB / MT);   // 32 x 8 = 256 CTAs
    dim3 pgrid(27, CB / 8);    // 27 x 64

    int p = 0;
    for (int t = 0; t < CS; ++t) {
        lstm_step<<<sgrid, 256, SMEM_STEP>>>(0, t, p, p ^ 1);
        p ^= 1;
    }
    for (int s = 0; s < CML; ++s) {
        if (s == 0) lstm_step<<<sgrid, 256, SMEM_STEP>>>(0, CS - 1, p, p ^ 1);
        else        lstm_step<<<sgrid, 256, SMEM_STEP>>>(1, 0, p, p ^ 1);
        proj_kernel<<<pgrid, 256>>>(p ^ 1, W_out, b_out, out + (size_t)s * CD);
        p ^= 1;
    }
}